// round 3
// baseline (speedup 1.0000x reference)
#include <cuda_runtime.h>
#include <cstdint>

#define N_ROWS 512
#define D_COLS 256
#define EPS 1e-7f
#define CLUSTER_N 8
#define THREADS   1024
#define ROWS_PER_CTA (N_ROWS / CLUSTER_N)        // 64
#define ROWGROUPS    (THREADS / D_COLS)          // 4
#define ROWS_PER_THREAD (ROWS_PER_CTA / ROWGROUPS) // 16

__device__ __forceinline__ uint32_t smem_u32(const void* p) {
    return (uint32_t)__cvta_generic_to_shared(p);
}
__device__ __forceinline__ float dsmem_ld(uint32_t local_addr, uint32_t rank) {
    uint32_t ra; float v;
    asm("mapa.shared::cluster.u32 %0, %1, %2;" : "=r"(ra) : "r"(local_addr), "r"(rank));
    asm volatile("ld.shared::cluster.f32 %0, [%1];" : "=f"(v) : "r"(ra));
    return v;
}
__device__ __forceinline__ void cluster_sync() {
    asm volatile("barrier.cluster.arrive.aligned;" ::: "memory");
    asm volatile("barrier.cluster.wait.aligned;"   ::: "memory");
}
__device__ __forceinline__ uint32_t cta_rank() {
    uint32_t r; asm("mov.u32 %0, %%cluster_ctarank;" : "=r"(r)); return r;
}

__global__ void __launch_bounds__(THREADS, 1) __cluster_dims__(CLUSTER_N, 1, 1)
club_cluster_kernel(const float* __restrict__ mu,
                    const float* __restrict__ logvar,
                    const float* __restrict__ h,
                    float* __restrict__ out) {
    const int tid = threadIdx.x;
    const int col = tid & (D_COLS - 1);   // 0..255
    const int rg  = tid >> 8;             // 0..3
    const uint32_t rank = cta_rank();

    // ---- Phase 1: per-thread accumulation over 16 rows (coalesced) ----
    const int row0 = (int)rank * ROWS_PER_CTA + rg * ROWS_PER_THREAD;
    float s1 = 0.f, s2 = 0.f, a = 0.f, b = 0.f, c = 0.f;
#pragma unroll
    for (int r = 0; r < ROWS_PER_THREAD; ++r) {
        const int idx = (row0 + r) * D_COLS + col;
        const float hv = h[idx];
        const float mv = mu[idx];
        const float lv = logvar[idx];
        const float inv = 1.0f / (__expf(lv) + EPS);
        s1 += hv;
        s2 += hv * hv;
        a  += inv * mv;
        b  += inv;
        const float dmh = mv - hv;
        c  += inv * (dmh * dmh - mv * mv);
    }

    // ---- Phase 2: intra-CTA reduce 4 rowgroups -> part[5][256] ----
    __shared__ float red[2][5][D_COLS];   // 10 KB staging
    __shared__ float part[5][D_COLS];     // 5 KB published partials

    if (rg >= 2) {
        float* p = &red[rg - 2][0][col];
        p[0*D_COLS] = s1; p[1*D_COLS] = s2; p[2*D_COLS] = a;
        p[3*D_COLS] = b;  p[4*D_COLS] = c;
    }
    __syncthreads();
    if (rg < 2) {
        const float* p = &red[rg][0][col];
        s1 += p[0*D_COLS]; s2 += p[1*D_COLS]; a += p[2*D_COLS];
        b  += p[3*D_COLS]; c  += p[4*D_COLS];
    }
    __syncthreads();
    if (rg == 1) {
        float* p = &red[0][0][col];
        p[0*D_COLS] = s1; p[1*D_COLS] = s2; p[2*D_COLS] = a;
        p[3*D_COLS] = b;  p[4*D_COLS] = c;
    }
    __syncthreads();
    if (rg == 0) {
        const float* p = &red[0][0][col];
        part[0][col] = s1 + p[0*D_COLS];
        part[1][col] = s2 + p[1*D_COLS];
        part[2][col] = a  + p[2*D_COLS];
        part[3][col] = b  + p[3*D_COLS];
        part[4][col] = c  + p[4*D_COLS];
    }

    // ---- Phase 3: cluster barrier publishes all CTAs' part[][] ----
    cluster_sync();

    // ---- Phase 4: CTA 0 combines via DSMEM and writes the scalar ----
    if (rank == 0 && tid < D_COLS) {
        const uint32_t base = smem_u32(&part[0][col]);
        float S1 = 0.f, S2 = 0.f, A = 0.f, B = 0.f, C = 0.f;
#pragma unroll
        for (uint32_t r = 0; r < CLUSTER_N; ++r) {
            S1 += dsmem_ld(base + 0 * D_COLS * 4, r);
            S2 += dsmem_ld(base + 1 * D_COLS * 4, r);
            A  += dsmem_ld(base + 2 * D_COLS * 4, r);
            B  += dsmem_ld(base + 3 * D_COLS * 4, r);
            C  += dsmem_ld(base + 4 * D_COLS * 4, r);
        }
        const float invN = 1.0f / (float)N_ROWS;
        float term = C + 2.0f * (S1 * invN) * A - (S2 * invN) * B;

#pragma unroll
        for (int s = 16; s > 0; s >>= 1)
            term += __shfl_xor_sync(0xFFFFFFFFu, term, s);

        __shared__ float warpsum[8];
        if ((tid & 31) == 0) warpsum[tid >> 5] = term;
        __syncwarp();
        // cross-warp combine done by thread 0 after a block-level sync below
        // (only warps 0-7 of CTA0 participate here; use bar.sync on 256 threads)
        asm volatile("bar.sync 1, %0;" :: "r"(D_COLS) : "memory");
        if (tid == 0) {
            float tot = 0.f;
#pragma unroll
            for (int w = 0; w < 8; ++w) tot += warpsum[w];
            out[0] = -0.5f * invN * tot;
        }
    }

    // ---- Phase 5: keep smem alive until CTA0 finished reading ----
    cluster_sync();
}

extern "C" void kernel_launch(void* const* d_in, const int* in_sizes, int n_in,
                              void* d_out, int out_size) {
    const float* mu     = (const float*)d_in[0];
    const float* logvar = (const float*)d_in[1];
    const float* h      = (const float*)d_in[2];
    float* out          = (float*)d_out;
    club_cluster_kernel<<<CLUSTER_N, THREADS>>>(mu, logvar, h, out);
}

// round 4
// speedup vs baseline: 1.0238x; 1.0238x over previous
#include <cuda_runtime.h>

#define N_ROWS 512
#define D_COLS 256
#define EPS 1e-7f
#define NBLK 64
#define ROWS_PER_BLK (N_ROWS / NBLK)   // 8

// Accumulators: zeroed at module load; the finisher block resets them each
// call so graph replays see zeros. No device allocation anywhere.
__device__ float gS1[D_COLS];
__device__ float gS2[D_COLS];
__device__ float gA[D_COLS];
__device__ float gB[D_COLS];
__device__ float gC[D_COLS];
__device__ unsigned int gCounter;

__global__ void __launch_bounds__(D_COLS)
club_fused2(const float* __restrict__ mu,
            const float* __restrict__ logvar,
            const float* __restrict__ h,
            float* __restrict__ out) {
    const int d  = threadIdx.x;                 // column 0..255
    const int r0 = blockIdx.x * ROWS_PER_BLK;

    float s1 = 0.f, s2 = 0.f, a = 0.f, b = 0.f, c = 0.f;

#pragma unroll
    for (int r = 0; r < ROWS_PER_BLK; ++r) {
        const int idx = (r0 + r) * D_COLS + d;  // coalesced row-major
        const float hv = h[idx];
        const float mv = mu[idx];
        const float lv = logvar[idx];
        const float inv = 1.0f / (__expf(lv) + EPS);
        s1 += hv;
        s2 += hv * hv;
        a  += inv * mv;
        b  += inv;
        c  += inv * hv * (hv - 2.0f * mv);      // == inv*((mu-h)^2 - mu^2)
    }

    // Fire-and-forget column reductions (results unused -> REDG).
    atomicAdd(&gS1[d], s1);
    atomicAdd(&gS2[d], s2);
    atomicAdd(&gA[d],  a);
    atomicAdd(&gB[d],  b);
    atomicAdd(&gC[d],  c);

    // Ticket: all threads' REDGs ordered via bar, promoted to gpu scope by
    // thread 0's fence (cumulative), then counted.
    __shared__ bool isLast;
    __syncthreads();
    if (d == 0) {
        __threadfence();
        isLast = (atomicAdd(&gCounter, 1u) == NBLK - 1);
    }
    __syncthreads();
    if (!isLast) return;

    // counter==NBLK-1 implies every block's fence completed, so all REDGs are
    // visible in L2. __ldcg reads L2 directly (no stale L1 risk), pipelined.
    const float S1 = __ldcg(&gS1[d]);
    const float S2 = __ldcg(&gS2[d]);
    const float A  = __ldcg(&gA[d]);
    const float B  = __ldcg(&gB[d]);
    const float C  = __ldcg(&gC[d]);

    const float invN = 1.0f / (float)N_ROWS;
    float term = C + 2.0f * (S1 * invN) * A - (S2 * invN) * B;

    // 5 shuffles + one smem hop instead of an 8-sync smem tree.
#pragma unroll
    for (int s = 16; s > 0; s >>= 1)
        term += __shfl_xor_sync(0xFFFFFFFFu, term, s);

    __shared__ float warpsum[8];
    if ((d & 31) == 0) warpsum[d >> 5] = term;
    __syncthreads();

    if (d == 0) {
        float tot = warpsum[0] + warpsum[1] + warpsum[2] + warpsum[3]
                  + warpsum[4] + warpsum[5] + warpsum[6] + warpsum[7];
        out[0]   = -0.5f * invN * tot;
        gCounter = 0u;                          // reset ticket for next replay
    }
    // Reset accumulators for the next replay (kernel boundary orders this
    // before the next launch's reads).
    gS1[d] = 0.f; gS2[d] = 0.f; gA[d] = 0.f; gB[d] = 0.f; gC[d] = 0.f;
}

extern "C" void kernel_launch(void* const* d_in, const int* in_sizes, int n_in,
                              void* d_out, int out_size) {
    const float* mu     = (const float*)d_in[0];
    const float* logvar = (const float*)d_in[1];
    const float* h      = (const float*)d_in[2];
    float* out          = (float*)d_out;
    club_fused2<<<NBLK, D_COLS>>>(mu, logvar, h, out);
}

// round 5
// speedup vs baseline: 1.2286x; 1.2000x over previous
#include <cuda_runtime.h>
#include <cstdint>

#define N_ROWS 512
#define D_COLS 256
#define EPS 1e-7f
#define NBLK 32
#define THREADS 512
#define ROWGROUPS 2
#define ROWS_PER_BLK (N_ROWS / NBLK)                  // 16
#define ROWS_PER_THREAD (ROWS_PER_BLK / ROWGROUPS)    // 8

// Accumulators: zeroed at module load; finisher resets them each call so
// graph replays see zeros. No device allocation anywhere.
__device__ float gS1[D_COLS];
__device__ float gS2[D_COLS];
__device__ float gA[D_COLS];
__device__ float gB[D_COLS];
__device__ float gC[D_COLS];
__device__ unsigned int gCounter;

__global__ void __launch_bounds__(THREADS)
club_fused3(const float* __restrict__ mu,
            const float* __restrict__ logvar,
            const float* __restrict__ h,
            float* __restrict__ out) {
    const int tid = threadIdx.x;
    const int col = tid & (D_COLS - 1);               // 0..255
    const int rg  = tid >> 8;                         // 0..1
    const int r0  = blockIdx.x * ROWS_PER_BLK + rg * ROWS_PER_THREAD;

    float s1 = 0.f, s2 = 0.f, a = 0.f, b = 0.f, c = 0.f;

#pragma unroll
    for (int r = 0; r < ROWS_PER_THREAD; ++r) {
        const int idx = (r0 + r) * D_COLS + col;      // coalesced row-major
        const float hv = h[idx];
        const float mv = mu[idx];
        const float lv = logvar[idx];
        const float inv = 1.0f / (__expf(lv) + EPS);
        s1 += hv;
        s2 += hv * hv;
        a  += inv * mv;
        b  += inv;
        c  += inv * hv * (hv - 2.0f * mv);            // == inv*((mu-h)^2-mu^2)
    }

    // One smem stage: rowgroup 1 publishes, rowgroup 0 combines -> halves
    // the REDG traffic (only 256 threads/block hit global atomics).
    __shared__ float red[5][D_COLS];                  // 5 KB
    if (rg == 1) {
        red[0][col] = s1; red[1][col] = s2; red[2][col] = a;
        red[3][col] = b;  red[4][col] = c;
    }
    __syncthreads();
    if (rg == 0) {
        s1 += red[0][col]; s2 += red[1][col]; a += red[2][col];
        b  += red[3][col]; c  += red[4][col];
        // Fire-and-forget column reductions (relaxed REDG).
        atomicAdd(&gS1[col], s1);
        atomicAdd(&gS2[col], s2);
        atomicAdd(&gA[col],  a);
        atomicAdd(&gB[col],  b);
        atomicAdd(&gC[col],  c);
    }

    // Ticket: bar orders all intra-block REDGs before thread 0's RELEASE
    // atomic (cumulativity). The finisher's acq_rel on the same address
    // synchronizes-with every prior release -> all REDGs visible. This
    // replaces __threadfence (MEMBAR.GPU) + atomicAdd with ONE instruction.
    __shared__ bool isLast;
    __syncthreads();
    if (tid == 0) {
        unsigned int old;
        asm volatile("atom.acq_rel.gpu.global.add.u32 %0, [%1], %2;"
                     : "=r"(old) : "l"(&gCounter), "r"(1u) : "memory");
        isLast = (old == NBLK - 1);
    }
    __syncthreads();
    if (!isLast) return;

    // ---- finisher: combine 256 column totals -> scalar ----
    const float invN = 1.0f / (float)N_ROWS;
    float term = 0.f;
    if (tid < D_COLS) {
        const float S1 = __ldcg(&gS1[tid]);
        const float S2 = __ldcg(&gS2[tid]);
        const float A  = __ldcg(&gA[tid]);
        const float B  = __ldcg(&gB[tid]);
        const float C  = __ldcg(&gC[tid]);
        term = C + 2.0f * (S1 * invN) * A - (S2 * invN) * B;
    }

#pragma unroll
    for (int s = 16; s > 0; s >>= 1)
        term += __shfl_xor_sync(0xFFFFFFFFu, term, s);

    __shared__ float warpsum[THREADS / 32];           // 16
    if ((tid & 31) == 0) warpsum[tid >> 5] = term;
    __syncthreads();

    if (tid == 0) {
        float tot = 0.f;
#pragma unroll
        for (int w = 0; w < THREADS / 32; ++w) tot += warpsum[w];
        out[0]   = -0.5f * invN * tot;
        gCounter = 0u;                                // reset ticket
    }
    // Reset accumulators for the next replay (kernel boundary orders this).
    if (tid < D_COLS) {
        gS1[tid] = 0.f; gS2[tid] = 0.f; gA[tid] = 0.f;
        gB[tid]  = 0.f; gC[tid]  = 0.f;
    }
}

extern "C" void kernel_launch(void* const* d_in, const int* in_sizes, int n_in,
                              void* d_out, int out_size) {
    const float* mu     = (const float*)d_in[0];
    const float* logvar = (const float*)d_in[1];
    const float* h      = (const float*)d_in[2];
    float* out          = (float*)d_out;
    club_fused3<<<NBLK, THREADS>>>(mu, logvar, h, out);
}

// round 6
// speedup vs baseline: 1.2647x; 1.0294x over previous
#include <cuda_runtime.h>
#include <cstdint>

#define N_ROWS 512
#define D_COLS 256
#define EPS 1e-7f
#define NBLK 32
#define THREADS 512
#define COLS_PER_BLK (D_COLS / NBLK)      // 8
#define RGS 64                            // rowgroups per block (THREADS/8)
#define ROWS_PER_THREAD (N_ROWS / RGS)    // 8

// Only two scalars of global state. Zeroed at load; finisher resets each call.
__device__ float gPartial;
__device__ unsigned int gCounter;

__global__ void __launch_bounds__(THREADS)
club_colsplit(const float* __restrict__ mu,
              const float* __restrict__ logvar,
              const float* __restrict__ h,
              float* __restrict__ out) {
    const int tid  = threadIdx.x;
    const int lane = tid & 31;
    const int w    = tid >> 5;            // warp 0..15
    const int col  = tid & (COLS_PER_BLK - 1);        // 0..7
    const int rg   = tid >> 3;            // 0..63
    const int colg = blockIdx.x * COLS_PER_BLK + col; // global column

    // ---- Phase 1: each thread walks 8 rows of its column (sector-coalesced:
    // 8 consecutive lanes read 32B contiguous; warp = 4 sectors/LDG) ----
    float s1 = 0.f, s2 = 0.f, a = 0.f, b = 0.f, c = 0.f;
#pragma unroll
    for (int r = 0; r < ROWS_PER_THREAD; ++r) {
        const int idx = (rg * ROWS_PER_THREAD + r) * D_COLS + colg;
        const float hv = h[idx];
        const float mv = mu[idx];
        const float lv = logvar[idx];
        const float inv = 1.0f / (__expf(lv) + EPS);
        s1 += hv;
        s2 += hv * hv;
        a  += inv * mv;
        b  += inv;
        c  += inv * hv * (hv - 2.0f * mv);   // == inv*((mu-h)^2 - mu^2)
    }

    // ---- Phase 2: reduce the warp's 4 rowgroups (xor 8,16 keeps same col) ----
#pragma unroll
    for (int s = 8; s <= 16; s <<= 1) {
        s1 += __shfl_xor_sync(0xFFFFFFFFu, s1, s);
        s2 += __shfl_xor_sync(0xFFFFFFFFu, s2, s);
        a  += __shfl_xor_sync(0xFFFFFFFFu, a,  s);
        b  += __shfl_xor_sync(0xFFFFFFFFu, b,  s);
        c  += __shfl_xor_sync(0xFFFFFFFFu, c,  s);
    }

    // ---- Phase 3: 16 warps publish lane0-7 partials; warp 0 finishes ----
    __shared__ float part[16][5][COLS_PER_BLK];   // 2.5 KB
    if (lane < COLS_PER_BLK) {
        part[w][0][col] = s1; part[w][1][col] = s2; part[w][2][col] = a;
        part[w][3][col] = b;  part[w][4][col] = c;
    }
    __syncthreads();
    if (w != 0) return;

    // Warp 0: lane = colq + 8*k, k=0..3; each lane sums 4 of the 16 warps,
    // then xor 8,16 collapses k -> lanes 0-7 hold full column totals.
    const int colq = lane & 7;
    const int k    = lane >> 3;
    float S1 = 0.f, S2 = 0.f, A = 0.f, B = 0.f, C = 0.f;
#pragma unroll
    for (int j = 0; j < 4; ++j) {
        const int ww = k + 4 * j;
        S1 += part[ww][0][colq]; S2 += part[ww][1][colq];
        A  += part[ww][2][colq]; B  += part[ww][3][colq];
        C  += part[ww][4][colq];
    }
#pragma unroll
    for (int s = 8; s <= 16; s <<= 1) {
        S1 += __shfl_xor_sync(0xFFFFFFFFu, S1, s);
        S2 += __shfl_xor_sync(0xFFFFFFFFu, S2, s);
        A  += __shfl_xor_sync(0xFFFFFFFFu, A,  s);
        B  += __shfl_xor_sync(0xFFFFFFFFu, B,  s);
        C  += __shfl_xor_sync(0xFFFFFFFFu, C,  s);
    }

    const float invN = 1.0f / (float)N_ROWS;
    float term = 0.f;
    if (lane < COLS_PER_BLK)
        term = C + 2.0f * (S1 * invN) * A - (S2 * invN) * B;
    // Sum the 8 column terms (xor 1,2,4 stays within lanes 0-7).
#pragma unroll
    for (int s = 1; s <= 4; s <<= 1)
        term += __shfl_xor_sync(0xFFFFFFFFu, term, s);

    if (lane == 0) {
        // One scalar REDG per block; release via the acq_rel ticket below.
        atomicAdd(&gPartial, term);
        unsigned int old;
        asm volatile("atom.acq_rel.gpu.global.add.u32 %0, [%1], %2;"
                     : "=r"(old) : "l"(&gCounter), "r"(1u) : "memory");
        if (old == NBLK - 1) {
            // Acquire above makes all 32 REDGs visible; read L2 directly.
            const float tot = __ldcg(&gPartial);
            out[0]   = -0.5f * invN * tot;
            gPartial = 0.f;      // reset for next graph replay
            gCounter = 0u;
        }
    }
}

extern "C" void kernel_launch(void* const* d_in, const int* in_sizes, int n_in,
                              void* d_out, int out_size) {
    const float* mu     = (const float*)d_in[0];
    const float* logvar = (const float*)d_in[1];
    const float* h      = (const float*)d_in[2];
    float* out          = (float*)d_out;
    club_colsplit<<<NBLK, THREADS>>>(mu, logvar, h, out);
}

// round 7
// speedup vs baseline: 1.6000x; 1.2651x over previous
#include <cuda_runtime.h>
#include <cstdint>

#define N_ROWS 512
#define D_COLS 256
#define NBLK 32
#define THREADS 512
#define COLS_PER_BLK (D_COLS / NBLK)      // 8
#define ROWS_PER_THREAD (N_ROWS / (THREADS / COLS_PER_BLK))  // 8
#define SCALE_F 16777216.0f               // 2^24 fixed-point scale

// Single word of global state: high 58 bits = fixed-point sum, low 6 = count.
// Zeroed at module load; finisher resets it each call (replay-safe).
__device__ unsigned long long gPacked;

__global__ void __launch_bounds__(THREADS)
club_colsplit2(const float* __restrict__ mu,
               const float* __restrict__ logvar,
               const float* __restrict__ h,
               float* __restrict__ out) {
    const int tid  = threadIdx.x;
    const int lane = tid & 31;
    const int w    = tid >> 5;                        // warp 0..15
    const int col  = tid & (COLS_PER_BLK - 1);        // 0..7
    const int rg   = tid >> 3;                        // 0..63
    const int colg = blockIdx.x * COLS_PER_BLK + col; // global column

    // ---- Phase 1: 8 rows per thread, constant 1KB stride (imm offsets) ----
    const int base = rg * ROWS_PER_THREAD * D_COLS + colg;
    const float* __restrict__ hp = h      + base;
    const float* __restrict__ mp = mu     + base;
    const float* __restrict__ lp = logvar + base;

    float s1 = 0.f, s2 = 0.f, a = 0.f, b = 0.f, c = 0.f;
#pragma unroll
    for (int r = 0; r < ROWS_PER_THREAD; ++r) {
        const float hv = hp[r * D_COLS];
        const float mv = mp[r * D_COLS];
        const float lv = lp[r * D_COLS];
        // 1/(exp(lv)+1e-7) == exp(-lv) within 1.5e-5 rel (exp(lv) >= e^-5).
        const float inv = __expf(-lv);
        s1 += hv;
        s2 += hv * hv;
        a  += inv * mv;
        b  += inv;
        c  += inv * hv * (hv - 2.0f * mv);   // == inv*((mu-h)^2 - mu^2)
    }

    // ---- Phase 2: reduce warp's 4 rowgroups (xor 8,16 preserves col) ----
#pragma unroll
    for (int s = 8; s <= 16; s <<= 1) {
        s1 += __shfl_xor_sync(0xFFFFFFFFu, s1, s);
        s2 += __shfl_xor_sync(0xFFFFFFFFu, s2, s);
        a  += __shfl_xor_sync(0xFFFFFFFFu, a,  s);
        b  += __shfl_xor_sync(0xFFFFFFFFu, b,  s);
        c  += __shfl_xor_sync(0xFFFFFFFFu, c,  s);
    }

    // ---- Phase 3: 16 warps publish; warp 0 finishes the block ----
    __shared__ float part[16][5][COLS_PER_BLK];       // 2.5 KB
    if (lane < COLS_PER_BLK) {
        part[w][0][col] = s1; part[w][1][col] = s2; part[w][2][col] = a;
        part[w][3][col] = b;  part[w][4][col] = c;
    }
    __syncthreads();
    if (w != 0) return;

    const int colq = lane & 7;
    const int k    = lane >> 3;                       // 0..3
    float S1 = 0.f, S2 = 0.f, A = 0.f, B = 0.f, C = 0.f;
#pragma unroll
    for (int j = 0; j < 4; ++j) {
        const int ww = k + 4 * j;
        S1 += part[ww][0][colq]; S2 += part[ww][1][colq];
        A  += part[ww][2][colq]; B  += part[ww][3][colq];
        C  += part[ww][4][colq];
    }
#pragma unroll
    for (int s = 8; s <= 16; s <<= 1) {
        S1 += __shfl_xor_sync(0xFFFFFFFFu, S1, s);
        S2 += __shfl_xor_sync(0xFFFFFFFFu, S2, s);
        A  += __shfl_xor_sync(0xFFFFFFFFu, A,  s);
        B  += __shfl_xor_sync(0xFFFFFFFFu, B,  s);
        C  += __shfl_xor_sync(0xFFFFFFFFu, C,  s);
    }

    const float invN = 1.0f / (float)N_ROWS;
    float term = 0.f;
    if (lane < COLS_PER_BLK)
        term = C + 2.0f * (S1 * invN) * A - (S2 * invN) * B;
#pragma unroll
    for (int s = 1; s <= 4; s <<= 1)
        term += __shfl_xor_sync(0xFFFFFFFFu, term, s);

    if (lane == 0) {
        // ONE atomic carries both the value (fixed-point, bits 6..63) and the
        // arrival count (bits 0..5). The 32nd arriver holds the full sum in
        // old+myv -> no fence, no ticket, no readback.
        const long long fix = __float2ll_rn(term * SCALE_F);
        const unsigned long long myv =
            ((unsigned long long)fix << 6) + 1ull;
        const unsigned long long old = atomicAdd(&gPacked, myv);
        if ((old & 63ull) == (unsigned long long)(NBLK - 1)) {
            const long long tot = (long long)(old + myv); // 64*F + 32
            const long long F   = tot >> 6;               // exact: floor((64F+32)/64)=F
            const double val    = (double)F * (1.0 / (double)SCALE_F);
            out[0]  = (float)((-0.5 / (double)N_ROWS) * val);
            gPacked = 0ull;                               // reset for next replay
        }
    }
}

extern "C" void kernel_launch(void* const* d_in, const int* in_sizes, int n_in,
                              void* d_out, int out_size) {
    const float* mu     = (const float*)d_in[0];
    const float* logvar = (const float*)d_in[1];
    const float* h      = (const float*)d_in[2];
    float* out          = (float*)d_out;
    club_colsplit2<<<NBLK, THREADS>>>(mu, logvar, h, out);
}